// round 6
// baseline (speedup 1.0000x reference)
#include <cuda_runtime.h>
#include <math.h>
#include <stdint.h>

#define B    64
#define H    1024
#define NH   8
#define HD   128
#define SQ   24
#define NE   512
#define K3H  3072
#define H4   4096

#define LOGITS_TOT (SQ*B*NE)   // 786432
#define IDX_TOT    (SQ*B*3)    // 4608

#define KS_GATES 8
#define KS_QKV   8
#define KS_SMALL 16

// smem (floats): per stage: A_hi[64*20] A_lo[64*20] B_hi[256*20] B_lo[256*20]
#define SKP      20
#define AS_HI_F  0
#define AS_LO_F  1280
#define BS_HI_F  2560
#define BS_LO_F  7680
#define STAGE_F  12800
#define SMEM_MMA (2 * STAGE_F * 4)   // 102400 bytes

// ---------------- persistent device scratch (no allocations allowed) ----------------
__device__ float d_Wcat[(size_t)H4 * H4];     // [4096][4096] = W_ih | W_hh packed
__device__ float d_Xcat[(size_t)B * H4];      // [64][4096]  = x(3072) | h(1024)
__device__ float d_c[(size_t)B * H];
__device__ float d_gatesp[KS_GATES * (size_t)B * H4];
__device__ float d_qkvp[KS_QKV * (size_t)B * K3H];
__device__ float d_Kc[(size_t)SQ * B * H];
__device__ float d_Vc[(size_t)SQ * B * H];
__device__ float d_ctx[(size_t)B * H];
__device__ float d_aop[KS_SMALL * (size_t)B * H];
__device__ float d_qin[(size_t)B * H];
__device__ float d_qp[KS_SMALL * (size_t)B * H];

// ---------------- init kernels ----------------
__global__ void init_wcat(const float* __restrict__ W_ih, const float* __restrict__ W_hh) {
    size_t id = (size_t)blockIdx.x * 256 + threadIdx.x;   // 16.7M elems
    int j = (int)(id >> 12);
    int k = (int)(id & 4095);
    d_Wcat[id] = (k < K3H) ? W_ih[(size_t)j * K3H + k]
                           : W_hh[(size_t)j * H + (k - K3H)];
}

__global__ void init_state(const float* __restrict__ hidden,
                           const float* __restrict__ cell,
                           const float* __restrict__ init_in) {
    int id = blockIdx.x * 256 + threadIdx.x;              // B*H4 = 262144
    int b = id >> 12;
    int k = id & 4095;
    if (k < K3H) {
        d_Xcat[id] = init_in[(size_t)b * K3H + k];
    } else {
        d_Xcat[id] = hidden[(size_t)b * H + (k - K3H)];
        d_c[(size_t)b * H + (k - K3H)] = cell[(size_t)b * H + (k - K3H)];
    }
}

// ---------------- helpers ----------------
__device__ __forceinline__ void split4(float4 v, float4& h, float4& l) {
    uint32_t u;
    asm("cvt.rna.tf32.f32 %0, %1;" : "=r"(u) : "f"(v.x)); h.x = __uint_as_float(u);
    asm("cvt.rna.tf32.f32 %0, %1;" : "=r"(u) : "f"(v.y)); h.y = __uint_as_float(u);
    asm("cvt.rna.tf32.f32 %0, %1;" : "=r"(u) : "f"(v.z)); h.z = __uint_as_float(u);
    asm("cvt.rna.tf32.f32 %0, %1;" : "=r"(u) : "f"(v.w)); h.w = __uint_as_float(u);
    float rx = v.x - h.x, ry = v.y - h.y, rz = v.z - h.z, rw = v.w - h.w;
    asm("cvt.rna.tf32.f32 %0, %1;" : "=r"(u) : "f"(rx)); l.x = __uint_as_float(u);
    asm("cvt.rna.tf32.f32 %0, %1;" : "=r"(u) : "f"(ry)); l.y = __uint_as_float(u);
    asm("cvt.rna.tf32.f32 %0, %1;" : "=r"(u) : "f"(rz)); l.z = __uint_as_float(u);
    asm("cvt.rna.tf32.f32 %0, %1;" : "=r"(u) : "f"(rw)); l.w = __uint_as_float(u);
}

#define MMA(d, a0, a1, a2, a3, b0, b1)                                              \
    asm volatile(                                                                   \
        "mma.sync.aligned.m16n8k8.row.col.f32.tf32.tf32.f32 "                       \
        "{%0,%1,%2,%3}, {%4,%5,%6,%7}, {%8,%9}, {%0,%1,%2,%3};"                     \
        : "+f"(d[0]), "+f"(d[1]), "+f"(d[2]), "+f"(d[3])                            \
        : "r"(__float_as_uint(a0)), "r"(__float_as_uint(a1)),                       \
          "r"(__float_as_uint(a2)), "r"(__float_as_uint(a3)),                       \
          "r"(__float_as_uint(b0)), "r"(__float_as_uint(b1)))

// ---------------- 3xTF32 mma.sync GEMM ----------------
// C_part[ky][64][N] = A[64,kslice] * W[N,kslice]^T.  Block tile 64x256, k-chunk 16,
// 8 warps (4m x 2n), warp tile m16 x n128 (16 n8 tiles), double-buffered smem.
__global__ __launch_bounds__(256)
void mma_gemm(const float* __restrict__ A, int lda,
              const float* __restrict__ W, int K, int N,
              float* __restrict__ C, int kper)
{
    extern __shared__ __align__(16) float sm[];
    const int tx = threadIdx.x;
    const int lane = tx & 31;
    const int warp = tx >> 5;
    const int gid = lane >> 2, tid = lane & 3;
    const int m0 = (warp & 3) * 16;        // warp m-tile
    const int n0w = (warp >> 2) * 128;     // warp n-strip (within block tile)
    const int nblk = blockIdx.x * 256;
    const int k0 = blockIdx.y * kper;
    const int nch = kper / 16;

    // staging indices
    const int wrow = tx;                   // W row (0..255)
    const int arow = tx >> 2, akg = tx & 3;
    const float* Wp = W + (size_t)(nblk + wrow) * K + k0;
    const float* Ap = A + (size_t)arow * lda + k0 + akg * 4;

    float acc[16][4];
#pragma unroll
    for (int j = 0; j < 16; j++)
#pragma unroll
        for (int q = 0; q < 4; q++) acc[j][q] = 0.f;

    // prologue: stage 0
    {
        float4 wv[4], av;
#pragma unroll
        for (int i = 0; i < 4; i++)
            wv[i] = *reinterpret_cast<const float4*>(Wp + i * 4);
        av = *reinterpret_cast<const float4*>(Ap);
        float* bh = sm + BS_HI_F + wrow * SKP;
        float* bl = sm + BS_LO_F + wrow * SKP;
#pragma unroll
        for (int i = 0; i < 4; i++) {
            float4 hv, lv; split4(wv[i], hv, lv);
            *reinterpret_cast<float4*>(bh + i * 4) = hv;
            *reinterpret_cast<float4*>(bl + i * 4) = lv;
        }
        float4 hv, lv; split4(av, hv, lv);
        *reinterpret_cast<float4*>(sm + AS_HI_F + arow * SKP + akg * 4) = hv;
        *reinterpret_cast<float4*>(sm + AS_LO_F + arow * SKP + akg * 4) = lv;
    }
    __syncthreads();

    for (int ch = 0; ch < nch; ch++) {
        const int st = ch & 1;
        const float* S = sm + st * STAGE_F;
        float4 wv[4], av;
        if (ch + 1 < nch) {
            const int ko = (ch + 1) * 16;
#pragma unroll
            for (int i = 0; i < 4; i++)
                wv[i] = *reinterpret_cast<const float4*>(Wp + ko + i * 4);
            av = *reinterpret_cast<const float4*>(Ap + ko);
        }

#pragma unroll
        for (int k8 = 0; k8 < 16; k8 += 8) {
            const int ab = AS_HI_F + (m0 + gid) * SKP + k8 + tid;
            const int al_ = AS_LO_F + (m0 + gid) * SKP + k8 + tid;
            float ah0 = S[ab],            ah1 = S[ab + 8 * SKP];
            float ah2 = S[ab + 4],        ah3 = S[ab + 8 * SKP + 4];
            float aL0 = S[al_],           aL1 = S[al_ + 8 * SKP];
            float aL2 = S[al_ + 4],       aL3 = S[al_ + 8 * SKP + 4];
#pragma unroll
            for (int j = 0; j < 16; j++) {
                const int nb = (n0w + j * 8 + gid) * SKP + k8 + tid;
                float bh0 = S[BS_HI_F + nb], bh1 = S[BS_HI_F + nb + 4];
                float bL0 = S[BS_LO_F + nb], bL1 = S[BS_LO_F + nb + 4];
                MMA(acc[j], ah0, ah1, ah2, ah3, bh0, bh1);
                MMA(acc[j], ah0, ah1, ah2, ah3, bL0, bL1);
                MMA(acc[j], aL0, aL1, aL2, aL3, bh0, bh1);
            }
        }

        if (ch + 1 < nch) {
            float* Sn = sm + (st ^ 1) * STAGE_F;
            float* bh = Sn + BS_HI_F + wrow * SKP;
            float* bl = Sn + BS_LO_F + wrow * SKP;
#pragma unroll
            for (int i = 0; i < 4; i++) {
                float4 hv, lv; split4(wv[i], hv, lv);
                *reinterpret_cast<float4*>(bh + i * 4) = hv;
                *reinterpret_cast<float4*>(bl + i * 4) = lv;
            }
            float4 hv, lv; split4(av, hv, lv);
            *reinterpret_cast<float4*>(Sn + AS_HI_F + arow * SKP + akg * 4) = hv;
            *reinterpret_cast<float4*>(Sn + AS_LO_F + arow * SKP + akg * 4) = lv;
        }
        __syncthreads();
    }

    // epilogue: thread owns rows m0+gid, m0+gid+8; cols n0w + j*8 + 2*tid (+1)
    float* Cp = C + (size_t)blockIdx.y * B * N;
    const int r0 = m0 + gid, r1 = m0 + gid + 8;
#pragma unroll
    for (int j = 0; j < 16; j++) {
        const int n = nblk + n0w + j * 8 + tid * 2;
        *reinterpret_cast<float2*>(&Cp[(size_t)r0 * N + n]) = make_float2(acc[j][0], acc[j][1]);
        *reinterpret_cast<float2*>(&Cp[(size_t)r1 * N + n]) = make_float2(acc[j][2], acc[j][3]);
    }
}

// ---------------- pointwise / small kernels ----------------
__device__ __forceinline__ float sigmoidf_(float x) { return 1.f / (1.f + expf(-x)); }

__global__ void lstm_update(const float* __restrict__ b_ih, const float* __restrict__ b_hh) {
    int id = blockIdx.x * blockDim.x + threadIdx.x;  // B*H
    int b = id >> 10, j = id & 1023;
    size_t base = (size_t)b * H4;
    float gi = b_ih[j]        + b_hh[j];
    float gf = b_ih[1024 + j] + b_hh[1024 + j];
    float gg = b_ih[2048 + j] + b_hh[2048 + j];
    float go = b_ih[3072 + j] + b_hh[3072 + j];
#pragma unroll
    for (int s = 0; s < KS_GATES; s++) {
        const float* g = d_gatesp + (size_t)s * B * H4 + base;
        gi += g[j]; gf += g[1024 + j]; gg += g[2048 + j]; go += g[3072 + j];
    }
    float c = sigmoidf_(gf) * d_c[(size_t)b * H + j] + sigmoidf_(gi) * tanhf(gg);
    d_c[(size_t)b * H + j] = c;
    d_Xcat[base + K3H + j] = sigmoidf_(go) * tanhf(c);
}

__global__ __launch_bounds__(256) void qkv_attention(const float* __restrict__ ain_b, int t) {
    int b = blockIdx.x;
    __shared__ __align__(16) float sq[H];
    __shared__ float sc[NH][32];

    for (int j = threadIdx.x; j < K3H; j += 256) {
        float v = ain_b[j];
#pragma unroll
        for (int s = 0; s < KS_QKV; s++)
            v += d_qkvp[(size_t)s * B * K3H + (size_t)b * K3H + j];
        if (j < 1024)       sq[j] = v;
        else if (j < 2048)  d_Kc[((size_t)t * B + b) * H + (j - 1024)] = v;
        else                d_Vc[((size_t)t * B + b) * H + (j - 2048)] = v;
    }
    __syncthreads();

    int w = threadIdx.x >> 5;
    int l = threadIdx.x & 31;
    const float scale = 0.08838834764831845f;  // 1/sqrt(128)

    float4 q4 = *reinterpret_cast<const float4*>(&sq[w * HD + l * 4]);
    for (int s = 0; s <= t; s++) {
        float4 k4 = *reinterpret_cast<const float4*>(&d_Kc[((size_t)s * B + b) * H + w * HD + l * 4]);
        float p = q4.x * k4.x + q4.y * k4.y + q4.z * k4.z + q4.w * k4.w;
#pragma unroll
        for (int off = 16; off; off >>= 1) p += __shfl_xor_sync(0xffffffffu, p, off);
        if (l == 0) sc[w][s] = p * scale;
    }
    __syncwarp();
    float val = (l <= t) ? sc[w][l] : -3.0e38f;
    float mx = val;
#pragma unroll
    for (int off = 16; off; off >>= 1) mx = fmaxf(mx, __shfl_xor_sync(0xffffffffu, mx, off));
    float e = (l <= t) ? expf(val - mx) : 0.f;
    float se = e;
#pragma unroll
    for (int off = 16; off; off >>= 1) se += __shfl_xor_sync(0xffffffffu, se, off);
    float inv = 1.f / se;

    float cx0 = 0.f, cx1 = 0.f, cx2 = 0.f, cx3 = 0.f;
    for (int s = 0; s <= t; s++) {
        float a = __shfl_sync(0xffffffffu, e, s) * inv;
        float4 v4 = *reinterpret_cast<const float4*>(&d_Vc[((size_t)s * B + b) * H + w * HD + l * 4]);
        cx0 = fmaf(a, v4.x, cx0); cx1 = fmaf(a, v4.y, cx1);
        cx2 = fmaf(a, v4.z, cx2); cx3 = fmaf(a, v4.w, cx3);
    }
    float4 o4 = make_float4(cx0, cx1, cx2, cx3);
    *reinterpret_cast<float4*>(&d_ctx[(size_t)b * H + w * HD + l * 4]) = o4;
}

__global__ void make_qin(const float* __restrict__ aout_b) {
    int id = blockIdx.x * blockDim.x + threadIdx.x;  // B*H
    int k = id & 1023;
    float ao = aout_b[k];
#pragma unroll
    for (int s = 0; s < KS_SMALL; s++) ao += d_aop[(size_t)s * B * H + id];
    d_qin[id] = 0.5f * (d_Xcat[(size_t)(id >> 10) * H4 + K3H + k] + ao);
}

__global__ __launch_bounds__(256)
void logits_kernel(const float* __restrict__ enc, const float* __restrict__ qt_b,
                   float* __restrict__ out, int t) {
    int b = blockIdx.x, ch = blockIdx.y;
    __shared__ __align__(16) float q[H];
    for (int k = threadIdx.x; k < H; k += 256) {
        float v = qt_b[k];
#pragma unroll
        for (int s = 0; s < KS_SMALL; s++) v += d_qp[(size_t)s * B * H + (size_t)b * H + k];
        q[k] = v;
    }
    __syncthreads();
    int w = threadIdx.x >> 5, l = threadIdx.x & 31;
    for (int ni = 0; ni < 16; ni++) {
        int n = ch * 128 + w * 16 + ni;
        const float4* e4 = reinterpret_cast<const float4*>(&enc[((size_t)b * NE + n) * H]);
        float acc = 0.f;
#pragma unroll
        for (int r = 0; r < 8; r++) {
            float4 ev = e4[l + r * 32];
            float4 qv = *reinterpret_cast<const float4*>(&q[(l + r * 32) * 4]);
            acc += ev.x * qv.x + ev.y * qv.y + ev.z * qv.z + ev.w * qv.w;
        }
#pragma unroll
        for (int off = 16; off; off >>= 1) acc += __shfl_xor_sync(0xffffffffu, acc, off);
        if (l == 0) out[(size_t)t * B * NE + (size_t)b * NE + n] = acc;
    }
}

__global__ __launch_bounds__(128)
void top3_kernel(const float* __restrict__ enc, float* __restrict__ out, int t, int out_size) {
    int b = blockIdx.x;
    __shared__ float s[NE];
    __shared__ int si[3];
    const float* lg = out + (size_t)t * B * NE + (size_t)b * NE;
    for (int n = threadIdx.x; n < NE; n += 128) s[n] = lg[n];
    __syncthreads();
    if (threadIdx.x == 0) {
        float v0 = -3.0e38f, v1 = -3.0e38f, v2 = -3.0e38f;
        int i0 = 0, i1 = 0, i2 = 0;
        for (int n = 0; n < NE; n++) {
            float v = s[n];
            if (v > v0)      { v2 = v1; i2 = i1; v1 = v0; i1 = i0; v0 = v; i0 = n; }
            else if (v > v1) { v2 = v1; i2 = i1; v1 = v; i1 = n; }
            else if (v > v2) { v2 = v; i2 = n; }
        }
        int a0 = i0, a1 = i1, a2 = i2, tmp;
        if (a0 > a1) { tmp = a0; a0 = a1; a1 = tmp; }
        if (a1 > a2) { tmp = a1; a1 = a2; a2 = tmp; }
        if (a0 > a1) { tmp = a0; a0 = a1; a1 = tmp; }
        si[0] = a0; si[1] = a1; si[2] = a2;
        if (out_size >= LOGITS_TOT + IDX_TOT) {
            float* op = out + (size_t)LOGITS_TOT + (size_t)t * B * 3 + (size_t)b * 3;
            op[0] = (float)a0; op[1] = (float)a1; op[2] = (float)a2;
        }
    }
    __syncthreads();
    for (int r = 0; r < 3; r++) {
        const float4* src = reinterpret_cast<const float4*>(&enc[((size_t)b * NE + si[r]) * H]);
        float4* dst = reinterpret_cast<float4*>(&d_Xcat[(size_t)b * H4 + r * H]);
        for (int k = threadIdx.x; k < 256; k += 128) dst[k] = src[k];
    }
}

// ---------------- launch ----------------
extern "C" void kernel_launch(void* const* d_in, const int* in_sizes, int n_in,
                              void* d_out, int out_size) {
    const float* enc     = (const float*)d_in[0];
    const float* hidden  = (const float*)d_in[1];
    const float* cell    = (const float*)d_in[2];
    const float* init_in = (const float*)d_in[4];
    int base = (in_sizes[5] > 1000) ? 5 : 6;   // skip scalar max_steps if present
    const float* W_ih   = (const float*)d_in[base + 0];
    const float* b_ih   = (const float*)d_in[base + 1];
    const float* W_hh   = (const float*)d_in[base + 2];
    const float* b_hh   = (const float*)d_in[base + 3];
    const float* ain_w  = (const float*)d_in[base + 4];
    const float* ain_b  = (const float*)d_in[base + 5];
    const float* aout_w = (const float*)d_in[base + 6];
    const float* aout_b = (const float*)d_in[base + 7];
    const float* qt_w   = (const float*)d_in[base + 8];
    const float* qt_b   = (const float*)d_in[base + 9];
    float* out = (float*)d_out;

    float *pW, *pX, *pGates, *pQkv, *pCtx, *pAop, *pQin, *pQp;
    cudaGetSymbolAddress((void**)&pW,    d_Wcat);
    cudaGetSymbolAddress((void**)&pX,    d_Xcat);
    cudaGetSymbolAddress((void**)&pGates,d_gatesp);
    cudaGetSymbolAddress((void**)&pQkv,  d_qkvp);
    cudaGetSymbolAddress((void**)&pCtx,  d_ctx);
    cudaGetSymbolAddress((void**)&pAop,  d_aop);
    cudaGetSymbolAddress((void**)&pQin,  d_qin);
    cudaGetSymbolAddress((void**)&pQp,   d_qp);

    cudaFuncSetAttribute(mma_gemm, cudaFuncAttributeMaxDynamicSharedMemorySize, SMEM_MMA);

    init_wcat<<<65536, 256>>>(W_ih, W_hh);
    init_state<<<1024, 256>>>(hidden, cell, init_in);

    for (int t = 0; t < SQ; t++) {
        // LSTM gates: [64,4096] = Xcat @ Wcat^T; 16 n-blocks x KS 8 -> 128 CTAs, kslice 512
        mma_gemm<<<dim3(16, KS_GATES), 256, SMEM_MMA>>>(pX, H4, pW, H4, H4, pGates, H4 / KS_GATES);
        lstm_update<<<256, 256>>>(b_ih, b_hh);
        // QKV: [64,3072] = h @ ain_w^T; 12 x 8 -> 96 CTAs, kslice 128
        mma_gemm<<<dim3(12, KS_QKV), 256, SMEM_MMA>>>(pX + K3H, H4, ain_w, H, K3H, pQkv, H / KS_QKV);
        qkv_attention<<<64, 256>>>(ain_b, t);
        // attn_out: [64,1024] = ctx @ aout_w^T; 4 x 16 -> 64 CTAs, kslice 64
        mma_gemm<<<dim3(4, KS_SMALL), 256, SMEM_MMA>>>(pCtx, H, aout_w, H, H, pAop, H / KS_SMALL);
        make_qin<<<256, 256>>>(aout_b);
        // query: [64,1024] = qin @ qt_w^T; 4 x 16 -> 64 CTAs, kslice 64
        mma_gemm<<<dim3(4, KS_SMALL), 256, SMEM_MMA>>>(pQin, H, qt_w, H, H, pQp, H / KS_SMALL);
        logits_kernel<<<dim3(64, 4), 256>>>(enc, qt_b, out, t);
        top3_kernel<<<64, 128>>>(enc, out, t, out_size);
    }
}

// round 7
// speedup vs baseline: 1.1273x; 1.1273x over previous
#include <cuda_runtime.h>
#include <math.h>

#define B    64
#define H    1024
#define NH   8
#define HD   128
#define SQ   24
#define NE   512
#define K3H  3072
#define H4   4096

#define LOGITS_TOT (SQ*B*NE)   // 786432
#define IDX_TOT    (SQ*B*3)    // 4608

#define KS_GATES 16
#define KS_QKV   16
#define KS_SMALL 32

typedef unsigned long long ull;

// ---------------- persistent device scratch (no allocations allowed) ----------------
__device__ float d_Wcat[(size_t)H4 * H4];     // [4096][4096] = W_ih | W_hh packed
__device__ float d_Xcat[(size_t)B * H4];      // [64][4096]  = x(3072) | h(1024)
__device__ float d_c[(size_t)B * H];
__device__ float d_gatesp[KS_GATES * (size_t)B * H4];
__device__ float d_qkvp[KS_QKV * (size_t)B * K3H];
__device__ float d_Kc[(size_t)SQ * B * H];
__device__ float d_Vc[(size_t)SQ * B * H];
__device__ float d_ctx[(size_t)B * H];
__device__ float d_aop[KS_SMALL * (size_t)B * H];
__device__ float d_qin[(size_t)B * H];
__device__ float d_qp[KS_SMALL * (size_t)B * H];

// ---------------- packed f32x2 helpers ----------------
__device__ __forceinline__ ull pk2(float x, float y) {
    ull r;
    asm("mov.b64 %0, {%1,%2};" : "=l"(r) : "f"(x), "f"(y));
    return r;
}
__device__ __forceinline__ void fma2(ull& d, ull a, ull b) {
    asm("fma.rn.f32x2 %0, %1, %2, %3;" : "=l"(d) : "l"(a), "l"(b), "l"(d));
}
__device__ __forceinline__ float2 up2(ull v) {
    float2 r;
    asm("mov.b64 {%0,%1}, %2;" : "=f"(r.x), "=f"(r.y) : "l"(v));
    return r;
}

// ---------------- init kernels ----------------
__global__ void init_wcat(const float* __restrict__ W_ih, const float* __restrict__ W_hh) {
    size_t id = (size_t)blockIdx.x * 256 + threadIdx.x;   // 16.7M elems
    int j = (int)(id >> 12);
    int k = (int)(id & 4095);
    d_Wcat[id] = (k < K3H) ? W_ih[(size_t)j * K3H + k]
                           : W_hh[(size_t)j * H + (k - K3H)];
}

__global__ void init_state(const float* __restrict__ hidden,
                           const float* __restrict__ cell,
                           const float* __restrict__ init_in) {
    int id = blockIdx.x * 256 + threadIdx.x;              // B*H4 = 262144
    int b = id >> 12;
    int k = id & 4095;
    if (k < K3H) {
        d_Xcat[id] = init_in[(size_t)b * K3H + k];
    } else {
        d_Xcat[id] = hidden[(size_t)b * H + (k - K3H)];
        d_c[(size_t)b * H + (k - K3H)] = cell[(size_t)b * H + (k - K3H)];
    }
}

// ---------------- fp32 GEMM with packed FFMA2 ----------------
// C_part[ky][64][N] = A[64, kslice] * W[N, kslice]^T.
// Block tile 64x256, 128 threads, 8x16 microtile as 8x8 packed f32x2 accumulators.
// One fma.rn.f32x2 = 2 IEEE fp32 FMAs -> 2x the scalar FFMA issue ceiling.
__global__ __launch_bounds__(128)
void gemm64(const float* __restrict__ A, int lda,
            const float* __restrict__ W, int K, int N,
            float* __restrict__ C, int kper)
{
    __shared__ __align__(16) float As[2][16][72];
    __shared__ __align__(16) float Ws[2][16][260];

    const int tx = threadIdx.x;
    const int tm = tx >> 4;        // 0..7  -> rows tm*8 .. +7
    const int tn = tx & 15;        // 0..15 -> cols q*64 + tn*4 .. +3 (q=0..3)
    const int nblk = blockIdx.x * 256;
    const int k0 = blockIdx.y * kper;

    const int ldRow = tx >> 2;     // 0..31 (+i*32)
    const int ldKg  = tx & 3;      // k-group of 4 floats

    const float* Aptr = A + (size_t)ldRow * lda + k0 + ldKg * 4;
    const float* Wptr = W + (size_t)(nblk + ldRow) * K + k0 + ldKg * 4;

    ull acc[8][8];
#pragma unroll
    for (int i = 0; i < 8; i++)
#pragma unroll
        for (int j = 0; j < 8; j++) acc[i][j] = 0ull;

    const int nk = kper / 16;

    // prologue: fill stage 0
    {
#pragma unroll
        for (int i = 0; i < 2; i++) {
            float4 v = *reinterpret_cast<const float4*>(Aptr + (size_t)i * 32 * lda);
            int row = ldRow + i * 32;
            As[0][ldKg * 4 + 0][row] = v.x; As[0][ldKg * 4 + 1][row] = v.y;
            As[0][ldKg * 4 + 2][row] = v.z; As[0][ldKg * 4 + 3][row] = v.w;
        }
#pragma unroll
        for (int i = 0; i < 8; i++) {
            float4 v = *reinterpret_cast<const float4*>(Wptr + (size_t)i * 32 * K);
            int row = ldRow + i * 32;
            Ws[0][ldKg * 4 + 0][row] = v.x; Ws[0][ldKg * 4 + 1][row] = v.y;
            Ws[0][ldKg * 4 + 2][row] = v.z; Ws[0][ldKg * 4 + 3][row] = v.w;
        }
    }
    __syncthreads();

    for (int it = 0; it < nk; it++) {
        const int st = it & 1;
        float4 va[2], vw[8];
        if (it + 1 < nk) {
            const int koff = (it + 1) * 16;
#pragma unroll
            for (int i = 0; i < 2; i++)
                va[i] = *reinterpret_cast<const float4*>(Aptr + (size_t)i * 32 * lda + koff);
#pragma unroll
            for (int i = 0; i < 8; i++)
                vw[i] = *reinterpret_cast<const float4*>(Wptr + (size_t)i * 32 * K + koff);
        }
#pragma unroll
        for (int kk = 0; kk < 16; kk++) {
            float a[8];
            *reinterpret_cast<float4*>(&a[0]) = *reinterpret_cast<const float4*>(&As[st][kk][tm * 8]);
            *reinterpret_cast<float4*>(&a[4]) = *reinterpret_cast<const float4*>(&As[st][kk][tm * 8 + 4]);
            ull ap[8];
#pragma unroll
            for (int i = 0; i < 8; i++) ap[i] = pk2(a[i], a[i]);
#pragma unroll
            for (int q = 0; q < 4; q++) {
                const ull* bp = reinterpret_cast<const ull*>(&Ws[st][kk][q * 64 + tn * 4]);
                ull b0 = bp[0], b1 = bp[1];
#pragma unroll
                for (int i = 0; i < 8; i++) {
                    fma2(acc[i][q * 2 + 0], ap[i], b0);
                    fma2(acc[i][q * 2 + 1], ap[i], b1);
                }
            }
        }
        if (it + 1 < nk) {
            const int sn = st ^ 1;
#pragma unroll
            for (int i = 0; i < 2; i++) {
                int row = ldRow + i * 32;
                As[sn][ldKg * 4 + 0][row] = va[i].x; As[sn][ldKg * 4 + 1][row] = va[i].y;
                As[sn][ldKg * 4 + 2][row] = va[i].z; As[sn][ldKg * 4 + 3][row] = va[i].w;
            }
#pragma unroll
            for (int i = 0; i < 8; i++) {
                int row = ldRow + i * 32;
                Ws[sn][ldKg * 4 + 0][row] = vw[i].x; Ws[sn][ldKg * 4 + 1][row] = vw[i].y;
                Ws[sn][ldKg * 4 + 2][row] = vw[i].z; Ws[sn][ldKg * 4 + 3][row] = vw[i].w;
            }
        }
        __syncthreads();
    }

    float* Cp = C + (size_t)blockIdx.y * B * N;
#pragma unroll
    for (int i = 0; i < 8; i++) {
        const size_t rbase = (size_t)(tm * 8 + i) * N + nblk;
#pragma unroll
        for (int q = 0; q < 4; q++) {
            float2 lo = up2(acc[i][q * 2 + 0]);
            float2 hi = up2(acc[i][q * 2 + 1]);
            float4 v = make_float4(lo.x, lo.y, hi.x, hi.y);
            *reinterpret_cast<float4*>(&Cp[rbase + q * 64 + tn * 4]) = v;
        }
    }
}

// ---------------- pointwise / small kernels ----------------
__device__ __forceinline__ float sigmoidf_(float x) { return 1.f / (1.f + expf(-x)); }

__global__ void lstm_update(const float* __restrict__ b_ih, const float* __restrict__ b_hh) {
    int id = blockIdx.x * blockDim.x + threadIdx.x;  // B*H
    int b = id >> 10, j = id & 1023;
    size_t base = (size_t)b * H4;
    float gi = b_ih[j]        + b_hh[j];
    float gf = b_ih[1024 + j] + b_hh[1024 + j];
    float gg = b_ih[2048 + j] + b_hh[2048 + j];
    float go = b_ih[3072 + j] + b_hh[3072 + j];
#pragma unroll
    for (int s = 0; s < KS_GATES; s++) {
        const float* g = d_gatesp + (size_t)s * B * H4 + base;
        gi += g[j]; gf += g[1024 + j]; gg += g[2048 + j]; go += g[3072 + j];
    }
    float c = sigmoidf_(gf) * d_c[(size_t)b * H + j] + sigmoidf_(gi) * tanhf(gg);
    d_c[(size_t)b * H + j] = c;
    d_Xcat[base + K3H + j] = sigmoidf_(go) * tanhf(c);
}

// fused: sum qkv partials + bias, scatter K/V to cache, keep q in smem, run attention
__global__ __launch_bounds__(256) void qkv_attention(const float* __restrict__ ain_b, int t) {
    int b = blockIdx.x;
    __shared__ __align__(16) float sq[H];
    __shared__ float sc[NH][32];

    for (int j = threadIdx.x; j < K3H; j += 256) {
        float v = ain_b[j];
#pragma unroll
        for (int s = 0; s < KS_QKV; s++)
            v += d_qkvp[(size_t)s * B * K3H + (size_t)b * K3H + j];
        if (j < 1024)       sq[j] = v;
        else if (j < 2048)  d_Kc[((size_t)t * B + b) * H + (j - 1024)] = v;
        else                d_Vc[((size_t)t * B + b) * H + (j - 2048)] = v;
    }
    __syncthreads();

    int w = threadIdx.x >> 5;
    int l = threadIdx.x & 31;
    const float scale = 0.08838834764831845f;  // 1/sqrt(128)

    float4 q4 = *reinterpret_cast<const float4*>(&sq[w * HD + l * 4]);
    for (int s = 0; s <= t; s++) {
        float4 k4 = *reinterpret_cast<const float4*>(&d_Kc[((size_t)s * B + b) * H + w * HD + l * 4]);
        float p = q4.x * k4.x + q4.y * k4.y + q4.z * k4.z + q4.w * k4.w;
#pragma unroll
        for (int off = 16; off; off >>= 1) p += __shfl_xor_sync(0xffffffffu, p, off);
        if (l == 0) sc[w][s] = p * scale;
    }
    __syncwarp();
    float val = (l <= t) ? sc[w][l] : -3.0e38f;
    float mx = val;
#pragma unroll
    for (int off = 16; off; off >>= 1) mx = fmaxf(mx, __shfl_xor_sync(0xffffffffu, mx, off));
    float e = (l <= t) ? expf(val - mx) : 0.f;
    float se = e;
#pragma unroll
    for (int off = 16; off; off >>= 1) se += __shfl_xor_sync(0xffffffffu, se, off);
    float inv = 1.f / se;

    float cx0 = 0.f, cx1 = 0.f, cx2 = 0.f, cx3 = 0.f;
    for (int s = 0; s <= t; s++) {
        float a = __shfl_sync(0xffffffffu, e, s) * inv;
        float4 v4 = *reinterpret_cast<const float4*>(&d_Vc[((size_t)s * B + b) * H + w * HD + l * 4]);
        cx0 = fmaf(a, v4.x, cx0); cx1 = fmaf(a, v4.y, cx1);
        cx2 = fmaf(a, v4.z, cx2); cx3 = fmaf(a, v4.w, cx3);
    }
    float4 o4 = make_float4(cx0, cx1, cx2, cx3);
    *reinterpret_cast<float4*>(&d_ctx[(size_t)b * H + w * HD + l * 4]) = o4;
}

__global__ void make_qin(const float* __restrict__ aout_b) {
    int id = blockIdx.x * blockDim.x + threadIdx.x;  // B*H
    int k = id & 1023;
    float ao = aout_b[k];
#pragma unroll
    for (int s = 0; s < KS_SMALL; s++) ao += d_aop[(size_t)s * B * H + id];
    d_qin[id] = 0.5f * (d_Xcat[(size_t)(id >> 10) * H4 + K3H + k] + ao);
}

__global__ __launch_bounds__(256)
void logits_kernel(const float* __restrict__ enc, const float* __restrict__ qt_b,
                   float* __restrict__ out, int t) {
    int b = blockIdx.x, ch = blockIdx.y;
    __shared__ __align__(16) float q[H];
    for (int k = threadIdx.x; k < H; k += 256) {
        float v = qt_b[k];
#pragma unroll
        for (int s = 0; s < KS_SMALL; s++) v += d_qp[(size_t)s * B * H + (size_t)b * H + k];
        q[k] = v;
    }
    __syncthreads();
    int w = threadIdx.x >> 5, l = threadIdx.x & 31;
    for (int ni = 0; ni < 16; ni++) {
        int n = ch * 128 + w * 16 + ni;
        const float4* e4 = reinterpret_cast<const float4*>(&enc[((size_t)b * NE + n) * H]);
        float acc = 0.f;
#pragma unroll
        for (int r = 0; r < 8; r++) {
            float4 ev = e4[l + r * 32];
            float4 qv = *reinterpret_cast<const float4*>(&q[(l + r * 32) * 4]);
            acc += ev.x * qv.x + ev.y * qv.y + ev.z * qv.z + ev.w * qv.w;
        }
#pragma unroll
        for (int off = 16; off; off >>= 1) acc += __shfl_xor_sync(0xffffffffu, acc, off);
        if (l == 0) out[(size_t)t * B * NE + (size_t)b * NE + n] = acc;
    }
}

__global__ __launch_bounds__(128)
void top3_kernel(const float* __restrict__ enc, float* __restrict__ out, int t, int out_size) {
    int b = blockIdx.x;
    __shared__ float s[NE];
    __shared__ int si[3];
    const float* lg = out + (size_t)t * B * NE + (size_t)b * NE;
    for (int n = threadIdx.x; n < NE; n += 128) s[n] = lg[n];
    __syncthreads();
    if (threadIdx.x == 0) {
        float v0 = -3.0e38f, v1 = -3.0e38f, v2 = -3.0e38f;
        int i0 = 0, i1 = 0, i2 = 0;
        for (int n = 0; n < NE; n++) {
            float v = s[n];
            if (v > v0)      { v2 = v1; i2 = i1; v1 = v0; i1 = i0; v0 = v; i0 = n; }
            else if (v > v1) { v2 = v1; i2 = i1; v1 = v; i1 = n; }
            else if (v > v2) { v2 = v; i2 = n; }
        }
        int a0 = i0, a1 = i1, a2 = i2, tmp;
        if (a0 > a1) { tmp = a0; a0 = a1; a1 = tmp; }
        if (a1 > a2) { tmp = a1; a1 = a2; a2 = tmp; }
        if (a0 > a1) { tmp = a0; a0 = a1; a1 = tmp; }
        si[0] = a0; si[1] = a1; si[2] = a2;
        if (out_size >= LOGITS_TOT + IDX_TOT) {
            float* op = out + (size_t)LOGITS_TOT + (size_t)t * B * 3 + (size_t)b * 3;
            op[0] = (float)a0; op[1] = (float)a1; op[2] = (float)a2;
        }
    }
    __syncthreads();
    for (int r = 0; r < 3; r++) {
        const float4* src = reinterpret_cast<const float4*>(&enc[((size_t)b * NE + si[r]) * H]);
        float4* dst = reinterpret_cast<float4*>(&d_Xcat[(size_t)b * H4 + r * H]);
        for (int k = threadIdx.x; k < 256; k += 128) dst[k] = src[k];
    }
}

// ---------------- launch ----------------
extern "C" void kernel_launch(void* const* d_in, const int* in_sizes, int n_in,
                              void* d_out, int out_size) {
    const float* enc     = (const float*)d_in[0];
    const float* hidden  = (const float*)d_in[1];
    const float* cell    = (const float*)d_in[2];
    const float* init_in = (const float*)d_in[4];
    int base = (in_sizes[5] > 1000) ? 5 : 6;   // skip scalar max_steps if present
    const float* W_ih   = (const float*)d_in[base + 0];
    const float* b_ih   = (const float*)d_in[base + 1];
    const float* W_hh   = (const float*)d_in[base + 2];
    const float* b_hh   = (const float*)d_in[base + 3];
    const float* ain_w  = (const float*)d_in[base + 4];
    const float* ain_b  = (const float*)d_in[base + 5];
    const float* aout_w = (const float*)d_in[base + 6];
    const float* aout_b = (const float*)d_in[base + 7];
    const float* qt_w   = (const float*)d_in[base + 8];
    const float* qt_b   = (const float*)d_in[base + 9];
    float* out = (float*)d_out;

    float *pW, *pX, *pGates, *pQkv, *pCtx, *pAop, *pQin, *pQp;
    cudaGetSymbolAddress((void**)&pW,    d_Wcat);
    cudaGetSymbolAddress((void**)&pX,    d_Xcat);
    cudaGetSymbolAddress((void**)&pGates,d_gatesp);
    cudaGetSymbolAddress((void**)&pQkv,  d_qkvp);
    cudaGetSymbolAddress((void**)&pCtx,  d_ctx);
    cudaGetSymbolAddress((void**)&pAop,  d_aop);
    cudaGetSymbolAddress((void**)&pQin,  d_qin);
    cudaGetSymbolAddress((void**)&pQp,   d_qp);

    init_wcat<<<65536, 256>>>(W_ih, W_hh);
    init_state<<<1024, 256>>>(hidden, cell, init_in);

    for (int t = 0; t < SQ; t++) {
        // LSTM gates: [64,4096] = Xcat @ Wcat^T; 16 n-blocks x KS 16 -> 256 CTAs, kslice 256
        gemm64<<<dim3(16, KS_GATES), 128>>>(pX, H4, pW, H4, H4, pGates, H4 / KS_GATES);
        lstm_update<<<256, 256>>>(b_ih, b_hh);
        // QKV: [64,3072] = h @ ain_w^T; 12 x 16 -> 192 CTAs, kslice 64
        gemm64<<<dim3(12, KS_QKV), 128>>>(pX + K3H, H4, ain_w, H, K3H, pQkv, H / KS_QKV);
        qkv_attention<<<64, 256>>>(ain_b, t);
        // attn_out: [64,1024] = ctx @ aout_w^T; 4 x 32 -> 128 CTAs, kslice 32
        gemm64<<<dim3(4, KS_SMALL), 128>>>(pCtx, H, aout_w, H, H, pAop, H / KS_SMALL);
        make_qin<<<256, 256>>>(aout_b);
        // query: [64,1024] = qin @ qt_w^T; 4 x 32 -> 128 CTAs, kslice 32
        gemm64<<<dim3(4, KS_SMALL), 128>>>(pQin, H, qt_w, H, H, pQp, H / KS_SMALL);
        logits_kernel<<<dim3(64, 4), 256>>>(enc, qt_b, out, t);
        top3_kernel<<<64, 128>>>(enc, out, t, out_size);
    }
}